// round 14
// baseline (speedup 1.0000x reference)
#include <cuda_runtime.h>

// Problem shapes (fixed for this dataset entry)
#define B_   4
#define Q_   128
#define N_   50000
#define C_   20
#define BQ_  (B_ * Q_)          // 512
#define BN_  (B_ * N_)          // 200000
#define NV_  (N_ / 4)           // 12500 float4 per row
#define S_   10                 // producer chunks per row
#define CHUNK_ (NV_ / S_)       // 1250 float4 per chunk
#define NSTREAM_ 250            // threads 0..249 stream 5 float4 each (=1250)
#define GIDV_ (BN_ / 4)         // 50000 int4 for gid convert
#define GID_BLOCKS ((GIDV_ + 255) / 256)         // 196 flattened blocks

#define MIN_PTS_NUM  50
#define MIN_INST_CLS 4
#define FIXSCALE 16777216.0f    // 2^24 fixed-point (deterministic u64 sum)

// Output layout (fp32 concatenation, matching reference return order)
#define OFF_SCORES ((size_t)BQ_ * N_)            // 25,600,000
#define OFF_VALID  (OFF_SCORES + BQ_)
#define OFF_CLS    (OFF_VALID + BQ_)
#define OFF_GID    (OFF_CLS + BQ_)

// Scratch (no device allocation -> __device__ globals). Accumulated via
// relaxed atomics within a launch; the last-arriving block of each row reads
// the totals and resets everything to zero -> initial state restored every
// invocation (graph-replay safe).
__device__ int                g_cnt_tot[BQ_];
__device__ unsigned long long g_sum_tot[BQ_];
__device__ unsigned int       g_arrive[BQ_];

// Inline per-row argmax over C=20 class logits. Matches jnp.argmax first-max.
__device__ __forceinline__ int row_argmax(const float* __restrict__ p)
{
    float best = __ldg(&p[0]);
    int bi = 0;
    #pragma unroll
    for (int c = 1; c < C_; c++) {
        float v = __ldg(&p[c]);
        if (v > best) { best = v; bi = c; }
    }
    return bi;
}

// ---------------------------------------------------------------------------
// Single launch, grid (S_, BQ_) -- producers only, no spinner blocks.
//  Each block: one 1250-float4 chunk of row bq. Threads 0..249 stream
//  (5 float4 each, no bounds predicates). Selection is
//  sel = (logit>0)&(seg==cls) [sigmoid(x)>0.5 <=> x>0 -> no MUFU for select];
//  sigmoid only on selected (~2.5%). First 196 flattened blocks also convert
//  the gid slice (absorbed in the DRAM-bound stream).
//
//  Ordering (validated R13): thread 250 -- which issues no mask stores --
//  publishes block totals as relaxed atomics, then arrives with
//  atom.add.release.gpu (drains only its own ATOMGs, not the block's store
//  queue: the R11 mistake). The LAST arriver (prev==S_-1) becomes the row's
//  epilogue block: acquire-load, read totals, write score/valid/cls, reset
//  counters (all arrived -> race-free), and cooperatively re-zero the row in
//  the statistically never-taken cnt<50 instance-class case.
// ---------------------------------------------------------------------------
__global__ __launch_bounds__(256, 6)
void fused_kernel(const float* __restrict__ mask_logits,
                  const float* __restrict__ cls_logits,
                  const int* __restrict__ seg_pred,
                  const int* __restrict__ fg_idxs,
                  float* __restrict__ out_masks,
                  float* __restrict__ out_scores,
                  float* __restrict__ out_valid,
                  float* __restrict__ out_cls,
                  float* __restrict__ out_gid)
{
    const int chunk = blockIdx.x;
    const int bq    = blockIdx.y;
    const int tid   = threadIdx.x;
    const int fb    = bq * S_ + chunk;    // flattened block id

    // gid convert: coalesced int4 -> float4, first 196 blocks only.
    if (fb < GID_BLOCKS) {
        int vi = fb * 256 + tid;
        if (vi < GIDV_) {
            int4 v = __ldg(&reinterpret_cast<const int4*>(fg_idxs)[vi]);
            float4 f;
            f.x = (float)v.x; f.y = (float)v.y;
            f.z = (float)v.z; f.w = (float)v.w;
            reinterpret_cast<float4*>(out_gid)[vi] = f;
        }
    }

    const int b   = bq >> 7;              // / Q_
    const int cls = row_argmax(cls_logits + bq * C_);
    const size_t base = (size_t)bq * NV_ + (size_t)chunk * CHUNK_;

    float4* __restrict__ om = reinterpret_cast<float4*>(out_masks) + base;

    int   cnt  = 0;
    float ssum = 0.f;

    if (cls < MIN_INST_CLS) {
        const float4 z = make_float4(0.f, 0.f, 0.f, 0.f);
        if (tid < NSTREAM_) {
            #pragma unroll
            for (int k = 0; k < 5; k++)
                __stcs(&om[tid + k * NSTREAM_], z);
        }
    } else if (tid < NSTREAM_) {
        const float4* __restrict__ ml = reinterpret_cast<const float4*>(mask_logits) + base;
        const int4*   __restrict__ sp = reinterpret_cast<const int4*>(seg_pred) +
                                        (size_t)b * NV_ + (size_t)chunk * CHUNK_;

        // 5 (float4, int4) pairs, front-batched for MLP, no predicates.
        float4 x[5]; int4 s[5];
        #pragma unroll
        for (int k = 0; k < 5; k++) {
            int i = tid + k * NSTREAM_;
            x[k] = __ldcs(&ml[i]);
            s[k] = __ldg(&sp[i]);
        }
        #pragma unroll
        for (int k = 0; k < 5; k++) {
            int i = tid + k * NSTREAM_;
            bool s0 = (x[k].x > 0.f) & (s[k].x == cls);
            bool s1 = (x[k].y > 0.f) & (s[k].y == cls);
            bool s2 = (x[k].z > 0.f) & (s[k].z == cls);
            bool s3 = (x[k].w > 0.f) & (s[k].w == cls);
            float4 o;
            o.x = s0 ? 1.f : 0.f;
            o.y = s1 ? 1.f : 0.f;
            o.z = s2 ? 1.f : 0.f;
            o.w = s3 ? 1.f : 0.f;
            __stcs(&om[i], o);
            cnt += (int)s0 + (int)s1 + (int)s2 + (int)s3;
            if (s0 | s1 | s2 | s3) {
                if (s0) ssum += __fdividef(1.f, 1.f + __expf(-x[k].x));
                if (s1) ssum += __fdividef(1.f, 1.f + __expf(-x[k].y));
                if (s2) ssum += __fdividef(1.f, 1.f + __expf(-x[k].z));
                if (s3) ssum += __fdividef(1.f, 1.f + __expf(-x[k].w));
            }
        }
    }

    // Deterministic fixed-point conversion before reduction.
    unsigned long long fsum = (unsigned long long)(ssum * FIXSCALE + 0.5f);

    // Block reduction (8 warps); fixed tree -> deterministic.
    __shared__ int                scnt[8];
    __shared__ unsigned long long ssh[8];
    #pragma unroll
    for (int off = 16; off > 0; off >>= 1) {
        cnt  += __shfl_down_sync(0xFFFFFFFFu, cnt,  off);
        fsum += __shfl_down_sync(0xFFFFFFFFu, fsum, off);
    }
    int wid  = tid >> 5;
    int lane = tid & 31;
    if (lane == 0) { scnt[wid] = cnt; ssh[wid] = fsum; }
    __syncthreads();

    // Thread 250 (no mask stores in its queue): publish + release-arrive.
    __shared__ int s_last;
    if (tid == NSTREAM_) {
        if (cls >= MIN_INST_CLS) {
            int tc = 0; unsigned long long ts = 0ULL;
            #pragma unroll
            for (int w = 0; w < 8; w++) { tc += scnt[w]; ts += ssh[w]; }
            if (tc > 0) {
                atomicAdd(&g_cnt_tot[bq], tc);      // relaxed, L2-resident
                atomicAdd(&g_sum_tot[bq], ts);
            }
        }
        unsigned int prev;
        asm volatile("atom.add.release.gpu.global.u32 %0, [%1], %2;"
                     : "=r"(prev) : "l"(&g_arrive[bq]), "r"(1u) : "memory");
        s_last = (prev == S_ - 1);
    }
    __syncthreads();
    if (!s_last) return;

    // ---- epilogue: this is the row's last-arriving block ----
    __shared__ int s_flag;
    if (tid == 0) {
        unsigned int dummy;
        asm volatile("ld.acquire.gpu.global.u32 %0, [%1];"
                     : "=r"(dummy) : "l"(&g_arrive[bq]) : "memory");
        int                cnt_t = __ldcg(&g_cnt_tot[bq]);
        unsigned long long fs    = __ldcg(&g_sum_tot[bq]);
        const int v = (cnt_t >= MIN_PTS_NUM) && (cls >= MIN_INST_CLS);
        out_cls[bq]    = (float)cls;
        out_valid[bq]  = (float)v;
        float sum = (float)((double)fs * (1.0 / 16777216.0));
        out_scores[bq] = v ? sum / (float)cnt_t : 0.f;
        s_flag = (!v) && (cls >= MIN_INST_CLS);
        // Reset for next replay (all producers arrived -> race-free).
        g_cnt_tot[bq] = 0;
        g_sum_tot[bq] = 0ULL;
        g_arrive[bq]  = 0u;
    }
    __syncthreads();

    if (s_flag) {   // never with this data (cnt~1250 >> 50): safety net
        float4* __restrict__ zm = reinterpret_cast<float4*>(out_masks) +
                                  (size_t)bq * NV_;
        const float4 z = make_float4(0.f, 0.f, 0.f, 0.f);
        for (int i = tid; i < NV_; i += 256)
            __stcs(&zm[i], z);
    }
}

// ---------------------------------------------------------------------------
extern "C" void kernel_launch(void* const* d_in, const int* in_sizes, int n_in,
                              void* d_out, int out_size)
{
    const float* mask_logits = (const float*)d_in[0];   // [B,Q,N]  fp32
    const float* cls_logits  = (const float*)d_in[1];   // [B,Q,C]  fp32
    const int*   seg_pred    = (const int*)d_in[2];     // [B,N]    int32
    const int*   fg_idxs     = (const int*)d_in[3];     // [B*N]    int32
    float* out = (float*)d_out;

    float* out_masks  = out;
    float* out_scores = out + OFF_SCORES;
    float* out_valid  = out + OFF_VALID;
    float* out_cls    = out + OFF_CLS;
    float* out_gid    = out + OFF_GID;

    dim3 grid(S_, BQ_);
    fused_kernel<<<grid, 256>>>(mask_logits, cls_logits, seg_pred, fg_idxs,
                                out_masks, out_scores, out_valid,
                                out_cls, out_gid);
}

// round 15
// speedup vs baseline: 1.0107x; 1.0107x over previous
#include <cuda_runtime.h>

// Problem shapes (fixed for this dataset entry)
#define B_   4
#define Q_   128
#define N_   50000
#define C_   20
#define BQ_  (B_ * Q_)          // 512
#define BN_  (B_ * N_)          // 200000
#define NV_  (N_ / 4)           // 12500 float4 per row
#define S_   10                 // producer chunks per row
#define CHUNK_ (NV_ / S_)       // 1250 float4 per chunk
#define NSTREAM_ 250            // threads 0..249 stream 5 float4 each (=1250)
#define NPROD_ (BQ_ * S_)       // 5120 producer blocks
#define NEPI_  2                // 2 epilogue blocks (512 threads = 512 rows)
#define GIDV_ (BN_ / 4)         // 50000 int4 for gid convert
#define GID_BLOCKS ((GIDV_ + 255) / 256)         // 196 producer blocks

#define MIN_PTS_NUM  50
#define MIN_INST_CLS 4
#define FIXSCALE 16777216.0f    // 2^24 fixed-point (deterministic u64 sum)

// Output layout (fp32 concatenation, matching reference return order)
#define OFF_SCORES ((size_t)BQ_ * N_)            // 25,600,000
#define OFF_VALID  (OFF_SCORES + BQ_)
#define OFF_CLS    (OFF_VALID + BQ_)
#define OFF_GID    (OFF_CLS + BQ_)

// Scratch (no device allocation -> __device__ globals). Accumulated via
// relaxed atomics within a launch; the epilogue thread of each row reads the
// totals (after all 10 arrivals) and resets them to zero -> initial state
// restored every invocation (graph-replay safe, deterministic: fixed-point
// integer atomics are order-independent).
__device__ int                g_cnt_tot[BQ_];
__device__ unsigned long long g_sum_tot[BQ_];
__device__ unsigned int       g_arrive[BQ_];

// Inline per-row argmax over C=20 class logits. Matches jnp.argmax first-max.
__device__ __forceinline__ int row_argmax(const float* __restrict__ p)
{
    float best = __ldg(&p[0]);
    int bi = 0;
    #pragma unroll
    for (int c = 1; c < C_; c++) {
        float v = __ldg(&p[c]);
        if (v > best) { best = v; bi = c; }
    }
    return bi;
}

// ---------------------------------------------------------------------------
// Single launch, flat grid of NEPI_+NPROD_ = 5122 blocks.
//
//  Blocks 0..1 (epilogue): thread t owns row bq = blockIdx.x*256 + t.
//    Spins (acquire + nanosleep backoff) until the row's 10 producers have
//    arrived, then: read totals, argmax, write score/valid/cls, reset the
//    row's counters. Only 2/888 resident slots stolen from producers (the
//    R13 fusion had 512 spinner blocks resident all kernel -> producers ran
//    at 42% of the machine; that was the regression mechanism).
//
//  Blocks 2..5121 (producers): one 1250-float4 chunk of row bq.
//    Threads 0..249 stream 5 float4 each (no bounds predicates); selection
//    sel = (logit>0)&(seg==cls) [sigmoid(x)>0.5 <=> x>0, no MUFU for
//    select]; sigmoid only on selected (~2.5%). First 196 producer blocks
//    also convert the gid slice. Thread 250 -- which issues NO mask stores --
//    publishes block totals as relaxed atomics then arrives with
//    fire-and-forget red.release.gpu (drains only its own ATOMGs, never the
//    block's store queue, and carries no result dependency -> block retires
//    immediately: fixes both the R11 fence drain and the R14 tail stall).
// ---------------------------------------------------------------------------
__global__ __launch_bounds__(256, 6)
void fused_kernel(const float* __restrict__ mask_logits,
                  const float* __restrict__ cls_logits,
                  const int* __restrict__ seg_pred,
                  const int* __restrict__ fg_idxs,
                  float* __restrict__ out_masks,
                  float* __restrict__ out_scores,
                  float* __restrict__ out_valid,
                  float* __restrict__ out_cls,
                  float* __restrict__ out_gid)
{
    const int tid = threadIdx.x;

    if (blockIdx.x < NEPI_) {
        // ---------------- epilogue: one thread per row ----------------
        const int bq = blockIdx.x * 256 + tid;   // 0..511

        unsigned int v;
        const unsigned int* ap = &g_arrive[bq];
        do {
            asm volatile("ld.acquire.gpu.global.u32 %0, [%1];"
                         : "=r"(v) : "l"(ap));
            if (v < S_) __nanosleep(256);
        } while (v < S_);

        int                cnt = __ldcg(&g_cnt_tot[bq]);
        unsigned long long fs  = __ldcg(&g_sum_tot[bq]);
        const int cls = row_argmax(cls_logits + bq * C_);
        const int val = (cnt >= MIN_PTS_NUM) && (cls >= MIN_INST_CLS);
        out_cls[bq]    = (float)cls;
        out_valid[bq]  = (float)val;
        float sum = (float)((double)fs * (1.0 / 16777216.0));
        out_scores[bq] = val ? sum / (float)cnt : 0.f;
        // Reset for next replay (all producers arrived -> race-free).
        g_cnt_tot[bq] = 0;
        g_sum_tot[bq] = 0ULL;
        g_arrive[bq]  = 0u;

        // Never-taken safety net (cnt~1250 >> 50 for instance classes):
        // single-thread zero of the row; slow but correct if it ever fires.
        if (!val && cls >= MIN_INST_CLS) {
            float4* __restrict__ zm = reinterpret_cast<float4*>(out_masks) +
                                      (size_t)bq * NV_;
            const float4 z = make_float4(0.f, 0.f, 0.f, 0.f);
            for (int i = 0; i < NV_; i++) __stcs(&zm[i], z);
        }
        return;
    }

    // ---------------- producer block ----------------
    const int fb    = blockIdx.x - NEPI_;     // 0..5119
    const int bq    = fb / S_;
    const int chunk = fb - bq * S_;

    // gid convert: coalesced int4 -> float4, first 196 producer blocks.
    if (fb < GID_BLOCKS) {
        int vi = fb * 256 + tid;
        if (vi < GIDV_) {
            int4 g = __ldg(&reinterpret_cast<const int4*>(fg_idxs)[vi]);
            float4 f;
            f.x = (float)g.x; f.y = (float)g.y;
            f.z = (float)g.z; f.w = (float)g.w;
            reinterpret_cast<float4*>(out_gid)[vi] = f;
        }
    }

    const int b   = bq >> 7;                  // / Q_
    const int cls = row_argmax(cls_logits + bq * C_);
    const size_t base = (size_t)bq * NV_ + (size_t)chunk * CHUNK_;

    float4* __restrict__ om = reinterpret_cast<float4*>(out_masks) + base;

    int   cnt  = 0;
    float ssum = 0.f;

    if (cls < MIN_INST_CLS) {
        const float4 z = make_float4(0.f, 0.f, 0.f, 0.f);
        if (tid < NSTREAM_) {
            #pragma unroll
            for (int k = 0; k < 5; k++)
                __stcs(&om[tid + k * NSTREAM_], z);
        }
    } else if (tid < NSTREAM_) {
        const float4* __restrict__ ml = reinterpret_cast<const float4*>(mask_logits) + base;
        const int4*   __restrict__ sp = reinterpret_cast<const int4*>(seg_pred) +
                                        (size_t)b * NV_ + (size_t)chunk * CHUNK_;

        // 5 (float4, int4) pairs, front-batched for MLP, no predicates.
        float4 x[5]; int4 s[5];
        #pragma unroll
        for (int k = 0; k < 5; k++) {
            int i = tid + k * NSTREAM_;
            x[k] = __ldcs(&ml[i]);
            s[k] = __ldg(&sp[i]);
        }
        #pragma unroll
        for (int k = 0; k < 5; k++) {
            int i = tid + k * NSTREAM_;
            bool s0 = (x[k].x > 0.f) & (s[k].x == cls);
            bool s1 = (x[k].y > 0.f) & (s[k].y == cls);
            bool s2 = (x[k].z > 0.f) & (s[k].z == cls);
            bool s3 = (x[k].w > 0.f) & (s[k].w == cls);
            float4 o;
            o.x = s0 ? 1.f : 0.f;
            o.y = s1 ? 1.f : 0.f;
            o.z = s2 ? 1.f : 0.f;
            o.w = s3 ? 1.f : 0.f;
            __stcs(&om[i], o);
            cnt += (int)s0 + (int)s1 + (int)s2 + (int)s3;
            if (s0 | s1 | s2 | s3) {
                if (s0) ssum += __fdividef(1.f, 1.f + __expf(-x[k].x));
                if (s1) ssum += __fdividef(1.f, 1.f + __expf(-x[k].y));
                if (s2) ssum += __fdividef(1.f, 1.f + __expf(-x[k].z));
                if (s3) ssum += __fdividef(1.f, 1.f + __expf(-x[k].w));
            }
        }
    }

    // Deterministic fixed-point conversion before reduction.
    unsigned long long fsum = (unsigned long long)(ssum * FIXSCALE + 0.5f);

    // Block reduction (8 warps); fixed tree -> deterministic.
    __shared__ int                scnt[8];
    __shared__ unsigned long long ssh[8];
    #pragma unroll
    for (int off = 16; off > 0; off >>= 1) {
        cnt  += __shfl_down_sync(0xFFFFFFFFu, cnt,  off);
        fsum += __shfl_down_sync(0xFFFFFFFFu, fsum, off);
    }
    int wid  = tid >> 5;
    int lane = tid & 31;
    if (lane == 0) { scnt[wid] = cnt; ssh[wid] = fsum; }
    __syncthreads();

    // Thread 250 (no mask stores in its queue): publish + release-arrive
    // with no result dependency -> block retires immediately.
    if (tid == NSTREAM_) {
        if (cls >= MIN_INST_CLS) {
            int tc = 0; unsigned long long ts = 0ULL;
            #pragma unroll
            for (int w = 0; w < 8; w++) { tc += scnt[w]; ts += ssh[w]; }
            if (tc > 0) {
                atomicAdd(&g_cnt_tot[bq], tc);      // relaxed, L2-resident
                atomicAdd(&g_sum_tot[bq], ts);
            }
        }
        asm volatile("red.release.gpu.global.add.u32 [%0], %1;"
                     :: "l"(&g_arrive[bq]), "r"(1u) : "memory");
    }
}

// ---------------------------------------------------------------------------
extern "C" void kernel_launch(void* const* d_in, const int* in_sizes, int n_in,
                              void* d_out, int out_size)
{
    const float* mask_logits = (const float*)d_in[0];   // [B,Q,N]  fp32
    const float* cls_logits  = (const float*)d_in[1];   // [B,Q,C]  fp32
    const int*   seg_pred    = (const int*)d_in[2];     // [B,N]    int32
    const int*   fg_idxs     = (const int*)d_in[3];     // [B*N]    int32
    float* out = (float*)d_out;

    float* out_masks  = out;
    float* out_scores = out + OFF_SCORES;
    float* out_valid  = out + OFF_VALID;
    float* out_cls    = out + OFF_CLS;
    float* out_gid    = out + OFF_GID;

    fused_kernel<<<NEPI_ + NPROD_, 256>>>(mask_logits, cls_logits, seg_pred,
                                          fg_idxs, out_masks, out_scores,
                                          out_valid, out_cls, out_gid);
}